// round 5
// baseline (speedup 1.0000x reference)
#include <cuda_runtime.h>

// Problem constants (fixed shapes per reference)
#define KROWS 1025
#define F     8192
#define NCHUNK 128
#define ROWS_PER_CHUNK 8   // (KROWS-1)/NCHUNK = 1024/128

// Device scratch (no device-memory allocation in kernel_launch)
__device__ float g_partial[NCHUNK * F];   // 4 MB
__device__ float g_scale[F];

// Side stream + fork/join events, created once at library load (host objects,
// no device allocations inside kernel_launch).
static cudaStream_t g_side;
static cudaEvent_t  g_fork, g_done;
namespace {
struct StreamInit {
    StreamInit() {
        cudaStreamCreateWithFlags(&g_side, cudaStreamNonBlocking);
        cudaEventCreateWithFlags(&g_fork, cudaEventDisableTiming);
        cudaEventCreateWithFlags(&g_done, cudaEventDisableTiming);
    }
};
StreamInit g_stream_init;
}

// Kernel A (side stream, no dependencies): zero the F x F ext block EXCEPT the
// float4 that contains each row's diagonal element (finalize writes that one).
// 8 x float4 = 128 bytes per thread, pure streaming stores.
__global__ void relu_z_ext_zero(float* __restrict__ out) {
    int idx = blockIdx.x * blockDim.x + threadIdx.x;  // 0 .. F*F/32 - 1
    int row = idx >> 8;            // 256 chunks of 32 floats per row (F/32)
    int c   = idx & 255;
    int c4base = c << 3;           // first float4 index of this chunk
    int diag4  = row >> 2;         // float4 index holding the diagonal

    float4* p = (float4*)(out + (size_t)(KROWS + row) * F) + c4base;
    float4 z = make_float4(0.f, 0.f, 0.f, 0.f);
    #pragma unroll
    for (int j = 0; j < 8; ++j)
        if (c4base + j != diag4) p[j] = z;
}

// Kernel 1: partial column-wise sum of |x| over rows 1..1024.
// 128 row-chunks x float4 columns -> 1024 blocks, 262K threads.
__global__ void relu_z_partial_abs(const float* __restrict__ x) {
    int c4    = blockIdx.x * blockDim.x + threadIdx.x;  // 0..F/4-1
    int chunk = blockIdx.y;                             // 0..127
    int r0 = 1 + chunk * ROWS_PER_CHUNK;

    const float4* p = (const float4*)(x + (size_t)r0 * F) + c4;
    float4 s = make_float4(0.f, 0.f, 0.f, 0.f);
    #pragma unroll
    for (int r = 0; r < ROWS_PER_CHUNK; ++r) {
        float4 v = p[(size_t)r * (F / 4)];
        s.x += fabsf(v.x);
        s.y += fabsf(v.y);
        s.z += fabsf(v.z);
        s.w += fabsf(v.w);
    }
    ((float4*)(g_partial + chunk * F))[c4] = s;
}

// Kernel 2: finalize abssum -> scale; write center row AND the diagonal float4
// (bytes disjoint from relu_z_ext_zero, so no cross-stream ordering needed).
__global__ void relu_z_finalize(const float* __restrict__ x,
                                const float* __restrict__ lambdas,
                                float* __restrict__ out) {
    int f = blockIdx.x * blockDim.x + threadIdx.x;
    if (f >= F) return;
    float abssum = 0.0f;
    #pragma unroll 16
    for (int c = 0; c < NCHUNK; ++c) abssum += g_partial[c * F + f];

    float ctr = x[f];                 // x[0][f]
    float l = ctr - abssum;
    float u = ctr + abssum;
    float lam = lambdas[f];

    float pos   = (l > 0.0f) ? 1.0f : 0.0f;
    float cross = ((u > 0.0f) && (l < 0.0f)) ? 1.0f : 0.0f;
    float d     = fmaxf(-l * lam, u * (1.0f - lam));
    float scale = pos + cross * lam;
    float half  = 0.5f * cross * d;

    g_scale[f] = scale;
    out[f] = scale * ctr + half;      // center row

    // diagonal float4: zeros except lane (f & 3)
    float4 dv = make_float4(0.f, 0.f, 0.f, 0.f);
    ((float*)&dv)[f & 3] = half;
    ((float4*)(out + (size_t)(KROWS + f) * F))[f >> 2] = dv;
}

// Kernel 3: out[r] = scale * x[r] for r = 1..KROWS-1, float4 vectorized.
__global__ void relu_z_scale_rows(const float* __restrict__ x,
                                  float* __restrict__ out) {
    int idx = blockIdx.x * blockDim.x + threadIdx.x;
    const int per_row = F / 4;        // 2048
    int r = 1 + idx / per_row;
    int c4 = idx % per_row;
    if (r >= KROWS) return;

    float4 v = ((const float4*)(x + (size_t)r * F))[c4];
    float4 s = ((const float4*)g_scale)[c4];
    float4 o;
    o.x = s.x * v.x;
    o.y = s.y * v.y;
    o.z = s.z * v.z;
    o.w = s.w * v.w;
    ((float4*)(out + (size_t)r * F))[c4] = o;
}

extern "C" void kernel_launch(void* const* d_in, const int* in_sizes, int n_in,
                              void* d_out, int out_size) {
    const float* x       = (const float*)d_in[0];
    const float* lambdas = (const float*)d_in[1];
    float* out           = (float*)d_out;

    // Fork: ext-block zeroing runs on a side stream, concurrent with the
    // reduce/finalize/scale chain (no data dependency — diagonal float4s are
    // written only by finalize and skipped by the fill).
    cudaEventRecord(g_fork, 0);
    cudaStreamWaitEvent(g_side, g_fork, 0);
    {
        int total = F * (F / 32);            // 2,097,152 threads, 128 B each
        relu_z_ext_zero<<<total / 256, 256, 0, g_side>>>(out);
    }
    cudaEventRecord(g_done, g_side);

    // Main chain (capture stream):
    {
        dim3 grid(F / 4 / 256, NCHUNK);      // 8 x 128 = 1024 blocks
        relu_z_partial_abs<<<grid, 256>>>(x);
    }
    relu_z_finalize<<<F / 256, 256>>>(x, lambdas, out);
    {
        int total = (KROWS - 1) * (F / 4);   // 2,097,152
        relu_z_scale_rows<<<(total + 255) / 256, 256>>>(x, out);
    }

    // Join side stream back into the capture stream.
    cudaStreamWaitEvent(0, g_done, 0);
}

// round 6
// speedup vs baseline: 1.8287x; 1.8287x over previous
#include <cuda_runtime.h>

// Problem constants (fixed shapes per reference)
#define KROWS 1025
#define F     8192
#define NCHUNK 128
#define NBLK  592      // 4 blocks x 148 SMs, all co-resident
#define NTHR  256

// Device scratch (no device-memory allocation in kernel_launch)
__device__ float g_partial[NCHUNK * F];   // 4 MB
__device__ float g_scale[F];
__device__ unsigned g_arrive;    // cumulative arrivals (zero-init)
__device__ unsigned g_release;   // cumulative completed barriers (zero-init)

// Sense-free cumulative grid barrier. `target` = cumulative barrier index.
// Safe across graph replays: counters grow monotonically; each block reads its
// base before arriving at barrier 1, and no barrier completes before all
// blocks of this launch arrive.
__device__ __forceinline__ void grid_barrier(unsigned target) {
    __syncthreads();
    if (threadIdx.x == 0) {
        __threadfence();
        unsigned a = atomicAdd(&g_arrive, 1u) + 1u;
        if (a == target * NBLK) atomicMax(&g_release, target);
        while (*(volatile unsigned*)&g_release < target) __nanosleep(64);
        __threadfence();
    }
    __syncthreads();
}

__global__ void __launch_bounds__(NTHR, 4) relu_z_mega(
    const float* __restrict__ x,
    const float* __restrict__ lambdas,
    float* __restrict__ out)
{
    __shared__ unsigned s_base;
    if (threadIdx.x == 0) s_base = *(volatile unsigned*)&g_release;
    __syncthreads();
    const unsigned base = s_base;
    const int bid = blockIdx.x;
    const int tid = threadIdx.x;

    // ── Phase A: partial |x| column sums over rows 1..1024.
    // 1024 units: unit u = (chunk 0..127, c4blk 0..7); 256 threads x 8 rows x float4.
    for (int u = bid; u < 1024; u += NBLK) {
        int chunk = u >> 3;
        int c4    = ((u & 7) << 8) + tid;
        const float4* p = (const float4*)(x + (size_t)(1 + chunk * 8) * F) + c4;
        float4 s = make_float4(0.f, 0.f, 0.f, 0.f);
        #pragma unroll
        for (int r = 0; r < 8; ++r) {
            float4 v = p[(size_t)r * (F / 4)];
            s.x += fabsf(v.x);
            s.y += fabsf(v.y);
            s.z += fabsf(v.z);
            s.w += fabsf(v.w);
        }
        ((float4*)(g_partial + chunk * F))[c4] = s;
    }

    grid_barrier(base + 1);

    // ── Finalize (blocks 0..31): fold partials, scale/half, center row, diag.
    if (bid < 32) {
        int f = (bid << 8) + tid;
        float abssum = 0.0f;
        #pragma unroll 16
        for (int c = 0; c < NCHUNK; ++c) abssum += g_partial[c * F + f];

        float ctr = x[f];
        float l = ctr - abssum;
        float u = ctr + abssum;
        float lam = lambdas[f];

        float pos   = (l > 0.0f) ? 1.0f : 0.0f;
        float cross = ((u > 0.0f) && (l < 0.0f)) ? 1.0f : 0.0f;
        float d     = fmaxf(-l * lam, u * (1.0f - lam));
        float scale = pos + cross * lam;
        float half  = 0.5f * cross * d;

        g_scale[f] = scale;
        out[f] = scale * ctr + half;          // center row

        float4 dv = make_float4(0.f, 0.f, 0.f, 0.f);
        ((float*)&dv)[f & 3] = half;
        ((float4*)(out + (size_t)(KROWS + f) * F))[f >> 2] = dv;  // ext diagonal
    }

    grid_barrier(base + 2);

    // ── Store pass: body rows first (x still hot in L2), then ext zeros.
    // Unit = half a row (1024 float4); 4 float4 per thread.
    const int BODY_UNITS = 2048;                 // 1024 rows x 2 segments
    const int EXT_UNITS  = 16384;                // 8192 rows x 2 segments
    for (int uu = bid; uu < BODY_UNITS + EXT_UNITS; uu += NBLK) {
        if (uu < BODY_UNITS) {
            int r   = 1 + (uu >> 1);
            int c0  = ((uu & 1) << 10) + tid;
            const float4* xs = (const float4*)(x + (size_t)r * F);
            const float4* sc = (const float4*)g_scale;
            float4* os = (float4*)(out + (size_t)r * F);
            #pragma unroll
            for (int j = 0; j < 4; ++j) {
                int i = c0 + (j << 8);
                float4 v = xs[i];
                float4 s = sc[i];
                float4 o;
                o.x = s.x * v.x;
                o.y = s.y * v.y;
                o.z = s.z * v.z;
                o.w = s.w * v.w;
                os[i] = o;
            }
        } else {
            int e     = uu - BODY_UNITS;
            int row   = e >> 1;
            int diag4 = row >> 2;                // float4 slot owned by finalize
            int c0    = ((e & 1) << 10) + tid;
            float4* os = (float4*)(out + (size_t)(KROWS + row) * F);
            const float4 z = make_float4(0.f, 0.f, 0.f, 0.f);
            #pragma unroll
            for (int j = 0; j < 4; ++j) {
                int i = c0 + (j << 8);
                if (i != diag4) __stcs(&os[i], z);   // streaming: no L2 pollution
            }
        }
    }
}

extern "C" void kernel_launch(void* const* d_in, const int* in_sizes, int n_in,
                              void* d_out, int out_size) {
    const float* x       = (const float*)d_in[0];
    const float* lambdas = (const float*)d_in[1];
    float* out           = (float*)d_out;

    relu_z_mega<<<NBLK, NTHR>>>(x, lambdas, out);
}

// round 7
// speedup vs baseline: 2.2435x; 1.2269x over previous
#include <cuda_runtime.h>

// Problem constants (fixed shapes per reference)
#define KROWS 1025
#define F     8192
#define NCHUNK 128
#define ROWS_PER_CHUNK 8   // 1024/128

// Device scratch (no allocations in kernel_launch)
__device__ float g_partial[NCHUNK * F];   // 4 MB
__device__ float g_scale[F];

// Kernel 1: partial column-wise sum of |x| over rows 1..1024.
// 8 col-blocks x 128 row-chunks = 1024 blocks, 262K threads.
__global__ void relu_z_partial_abs(const float* __restrict__ x) {
    int c4    = blockIdx.x * blockDim.x + threadIdx.x;  // 0..F/4-1
    int chunk = blockIdx.y;                             // 0..127
    int r0 = 1 + chunk * ROWS_PER_CHUNK;

    const float4* p = (const float4*)(x + (size_t)r0 * F) + c4;
    float4 s = make_float4(0.f, 0.f, 0.f, 0.f);
    #pragma unroll
    for (int r = 0; r < ROWS_PER_CHUNK; ++r) {
        float4 v = p[(size_t)r * (F / 4)];
        s.x += fabsf(v.x);
        s.y += fabsf(v.y);
        s.z += fabsf(v.z);
        s.w += fabsf(v.w);
    }
    ((float4*)(g_partial + chunk * F))[c4] = s;
}

// Kernel 2: fold partials -> scale; write center row + ext diagonal float4.
__global__ void relu_z_finalize(const float* __restrict__ x,
                                const float* __restrict__ lambdas,
                                float* __restrict__ out) {
    int f = blockIdx.x * blockDim.x + threadIdx.x;
    float abssum = 0.0f;
    #pragma unroll 16
    for (int c = 0; c < NCHUNK; ++c) abssum += g_partial[c * F + f];

    float ctr = x[f];                 // x[0][f]
    float l = ctr - abssum;
    float u = ctr + abssum;
    float lam = lambdas[f];

    float pos   = (l > 0.0f) ? 1.0f : 0.0f;
    float cross = ((u > 0.0f) && (l < 0.0f)) ? 1.0f : 0.0f;
    float d     = fmaxf(-l * lam, u * (1.0f - lam));
    float scale = pos + cross * lam;
    float half  = 0.5f * cross * d;

    g_scale[f] = scale;
    out[f] = scale * ctr + half;      // center row

    // diagonal float4 of the ext block (store_all skips this slot)
    float4 dv = make_float4(0.f, 0.f, 0.f, 0.f);
    ((float*)&dv)[f & 3] = half;
    ((float4*)(out + (size_t)(KROWS + f) * F))[f >> 2] = dv;
}

// Kernel 3: ALL remaining stores in one launch.
// Unit = half a row = 1024 float4 = 256 threads x 4 float4.
//   blocks [0, 2048)      : body rows 1..1024, out = scale * x (x is L2-hot)
//   blocks [2048, 18432)  : ext rows, streaming zeros, skip diagonal float4
// Body units have the lowest block indices -> first wave, maximizing L2 reuse.
__global__ void __launch_bounds__(256) relu_z_store_all(
    const float* __restrict__ x, float* __restrict__ out) {
    const int b   = blockIdx.x;
    const int tid = threadIdx.x;

    if (b < 2048) {
        int r  = 1 + (b >> 1);
        int c0 = ((b & 1) << 10) + tid;
        const float4* xs = (const float4*)(x + (size_t)r * F);
        const float4* sc = (const float4*)g_scale;
        float4* os = (float4*)(out + (size_t)r * F);
        #pragma unroll
        for (int j = 0; j < 4; ++j) {
            int i = c0 + (j << 8);
            float4 v = xs[i];
            float4 s = sc[i];
            float4 o;
            o.x = s.x * v.x;
            o.y = s.y * v.y;
            o.z = s.z * v.z;
            o.w = s.w * v.w;
            __stcs(&os[i], o);             // out never re-read: bypass L2 fill
        }
    } else {
        int e     = b - 2048;
        int row   = e >> 1;
        int diag4 = row >> 2;              // owned by finalize
        int c0    = ((e & 1) << 10) + tid;
        float4* os = (float4*)(out + (size_t)(KROWS + row) * F);
        const float4 z = make_float4(0.f, 0.f, 0.f, 0.f);
        #pragma unroll
        for (int j = 0; j < 4; ++j) {
            int i = c0 + (j << 8);
            if (i != diag4) __stcs(&os[i], z);
        }
    }
}

extern "C" void kernel_launch(void* const* d_in, const int* in_sizes, int n_in,
                              void* d_out, int out_size) {
    const float* x       = (const float*)d_in[0];
    const float* lambdas = (const float*)d_in[1];
    float* out           = (float*)d_out;

    // 1) Partial abs-sums
    {
        dim3 grid(F / 4 / 256, NCHUNK);    // 8 x 128
        relu_z_partial_abs<<<grid, 256>>>(x);
    }
    // 2) Finalize: scale, center row, ext diagonal
    relu_z_finalize<<<F / 256, 256>>>(x, lambdas, out);
    // 3) Everything else: body rows + ext zeros, one launch
    relu_z_store_all<<<2048 + 16384, 256>>>(x, out);
}